// round 15
// baseline (speedup 1.0000x reference)
#include <cuda_runtime.h>
#include <cuda_fp16.h>
#include <float.h>
#include <math.h>
#include <cstdint>

#define N_NODES 131072
#define B_SEG   1024
#define H_DIM   128
#define TILE_N  128
#define NTILES  (N_NODES / TILE_N)
#define NSTAGES 3

// Tiles: [128 rows][136 halves] -> 272 B row stride (16B-aligned, 17x16B units)
#define A_STRIDE 136
#define B_STRIDE 136

__device__ float g_v[N_NODES];
__device__ int   g_off[B_SEG + 1];

// ---- k_node smem layout (bytes) ----
static constexpr int STAGE   = 34816;                   // A fp16 tile per stage
static constexpr int SM_B    = NSTAGES * STAGE;         // 104448
static constexpr int SM_FLT  = SM_B + 34816;            // 139264
// floats: lins[3][128]=384, ps[2][128][4]=1024, wls[384], b1s[128], w2s[128] = 2048
static constexpr int SMEM_K1 = SM_FLT + 2048 * 4;       // 147456

// ---------------------------------------------------------------------------
__device__ __forceinline__ uint32_t smem_u32(const void* p) {
    uint32_t a;
    asm("{ .reg .u64 t; cvta.to.shared.u64 t, %1; cvt.u32.u64 %0, t; }"
        : "=r"(a) : "l"(p));
    return a;
}
__device__ __forceinline__ void ldsm_x4(uint32_t* r, uint32_t a) {
    asm volatile("ldmatrix.sync.aligned.m8n8.x4.shared.b16 {%0,%1,%2,%3}, [%4];"
                 : "=r"(r[0]), "=r"(r[1]), "=r"(r[2]), "=r"(r[3]) : "r"(a));
}
__device__ __forceinline__ void ldsm_x2t(uint32_t* r, uint32_t a) {
    asm volatile("ldmatrix.sync.aligned.m8n8.x2.trans.shared.b16 {%0,%1}, [%2];"
                 : "=r"(r[0]), "=r"(r[1]) : "r"(a));
}
__device__ __forceinline__ void mma16816(float* d, const uint32_t* a, const uint32_t* b) {
    asm volatile(
        "mma.sync.aligned.m16n8k16.row.col.f32.f16.f16.f32 "
        "{%0,%1,%2,%3}, {%4,%5,%6,%7}, {%8,%9}, {%0,%1,%2,%3};"
        : "+f"(d[0]), "+f"(d[1]), "+f"(d[2]), "+f"(d[3])
        : "r"(a[0]), "r"(a[1]), "r"(a[2]), "r"(a[3]), "r"(b[0]), "r"(b[1]));
}

// ---------------------------------------------------------------------------
// Kernel 1: persistent pipelined node readout, double register buffer
// ---------------------------------------------------------------------------
__global__ __launch_bounds__(512, 1)
void k_node(const float4* __restrict__ emb4,
            const int*    __restrict__ batch,
            const float*  __restrict__ W_lins,
            const float*  __restrict__ b_lins,
            const float*  __restrict__ W1,
            const float*  __restrict__ b1,
            const float*  __restrict__ W2,
            const float*  __restrict__ b2)
{
    extern __shared__ __align__(16) char smem[];
    float* lins = (float*)(smem + SM_FLT);   // [3][128]
    float* ps   = lins + NSTAGES * 128;      // [2][128][4]
    float* wls  = ps + 1024;                 // [3][128]
    float* b1s  = wls + 384;                 // [128]
    float* w2s  = b1s + 128;                 // [128]

    const int tid  = threadIdx.x;
    const int lane = tid & 31;
    const int wid  = tid >> 5;
    const uint32_t sbase = smem_u32(smem);

    // ---- prelude: segment-offset scatter (batch sorted) ----
    for (int i = blockIdx.x * 512 + tid; i < N_NODES; i += gridDim.x * 512) {
        int b    = batch[i];
        int prev = (i == 0) ? -1 : batch[i - 1];
        for (int bb = prev + 1; bb <= b; ++bb) g_off[bb] = i;
        if (i == N_NODES - 1)
            for (int bb = b + 1; bb <= B_SEG; ++bb) g_off[bb] = N_NODES;
    }

    // one-time staging: W1 -> fp16 B tile; weights to smem
    {
        char* Bh = smem + SM_B;
        for (int i = tid; i < 128 * 128 / 4; i += 512) {
            float4 w = ((const float4*)W1)[i];
            int c  = i >> 5;
            int h4 = (i & 31) * 4;
            int off = (c * B_STRIDE + h4) * 2;
            *(__half2*)(Bh + off)     = __floats2half2_rn(w.x, w.y);
            *(__half2*)(Bh + off + 4) = __floats2half2_rn(w.z, w.w);
        }
    }
    for (int i = tid; i < 384; i += 512) wls[i] = W_lins[i];
    if (tid < 128) { b1s[tid] = b1[tid]; w2s[tid] = W2[tid]; }

    const int wm = wid >> 2;          // 0..3 -> rows wm*32
    const int wn = wid & 3;           // 0..3 -> cols wn*32
    const int lr = lane & 15;
    const int lk = (lane >> 4) * 8;
    const int gid = lane >> 2;
    const int tig = lane & 3;
    const float cst = b_lins[0] + b_lins[1] + b_lins[2] + b2[0];

    const uint32_t aB = sbase + SM_B;

    float4 xa[2][4], xb[2][4];

    #define LOAD_CHUNK(X_, n0_, nl_)                                         \
        do {                                                                 \
            _Pragma("unroll")                                                \
            for (int k_ = 0; k_ < 2; ++k_) {                                 \
                const float4* p_ = emb4 + (size_t)((n0_) + (nl_) + k_) * 128 + lane; \
                X_[k_][0] = p_[0];                                           \
                X_[k_][1] = p_[32];                                          \
                X_[k_][2] = p_[64];                                          \
                X_[k_][3] = p_[96];                                          \
            }                                                                \
        } while (0)

    #define CONV_CHUNK(X_, AhS_, linsS_, nl_)                                \
        do {                                                                 \
            _Pragma("unroll")                                                \
            for (int k_ = 0; k_ < 2; ++k_) {                                 \
                float l_ = 0.f;                                              \
                _Pragma("unroll")                                            \
                for (int cc_ = 0; cc_ < 4; ++cc_) {                          \
                    int c_ = cc_ * 32 + lane;                                \
                    l_ = fmaf(X_[k_][cc_].x, wls[c_],       l_);             \
                    l_ = fmaf(X_[k_][cc_].y, wls[128 + c_], l_);             \
                    l_ = fmaf(X_[k_][cc_].z, wls[256 + c_], l_);             \
                    *(__half*)((AhS_) + (((nl_) + k_) * A_STRIDE + c_) * 2) = \
                        __float2half_rn(X_[k_][cc_].w);                      \
                }                                                            \
                _Pragma("unroll")                                            \
                for (int d_ = 16; d_ > 0; d_ >>= 1)                          \
                    l_ += __shfl_xor_sync(0xffffffffu, l_, d_);              \
                if (lane == 0) (linsS_)[(nl_) + k_] = l_;                    \
            }                                                                \
        } while (0)

    #define MMA_K2(aA_, k0base_)                                             \
        do {                                                                 \
            _Pragma("unroll")                                                \
            for (int kk_ = 0; kk_ < 2; ++kk_) {                              \
                int k0_ = (k0base_) + kk_ * 16;                              \
                uint32_t bh_[4][2];                                          \
                _Pragma("unroll")                                            \
                for (int nt_ = 0; nt_ < 4; ++nt_) {                          \
                    uint32_t boff_ = (uint32_t)(((k0_ + lr) * B_STRIDE + wn * 32 + nt_ * 8) * 2); \
                    ldsm_x2t(bh_[nt_], aB + boff_);                          \
                }                                                            \
                _Pragma("unroll")                                            \
                for (int mt_ = 0; mt_ < 2; ++mt_) {                          \
                    uint32_t aoff_ = (uint32_t)(((wm * 32 + mt_ * 16 + lr) * A_STRIDE + k0_ + lk) * 2); \
                    uint32_t ah_[4];                                         \
                    ldsm_x4(ah_, (aA_) + aoff_);                             \
                    _Pragma("unroll")                                        \
                    for (int nt_ = 0; nt_ < 4; ++nt_)                        \
                        mma16816(acc[mt_][nt_], ah_, bh_[nt_]);              \
                }                                                            \
            }                                                                \
        } while (0)

    __syncthreads();

    // ---- prologue: load tile t0 into stage 0 ----
    int t = blockIdx.x;
    if (t < NTILES) {
        char*  Ah0   = smem;
        float* lins0 = lins;
        const int n0p = t * TILE_N;
        #pragma unroll 1
        for (int ch = 0; ch < 4; ++ch) {
            int nl = wid * 8 + ch * 2;
            LOAD_CHUNK(xa, n0p, nl);
            CONV_CHUNK(xa, Ah0, lins0, nl);
        }
    }
    __syncthreads();

    int it = 0;
    for (; t < NTILES; t += gridDim.x, ++it) {
        const int s0 = it % NSTAGES;
        const int s1 = (it + 1) % NSTAGES;
        const int n0 = t * TILE_N;
        const int tn = t + gridDim.x;
        const bool has_next = (tn < NTILES);
        const int n0n = tn * TILE_N;

        char*  AhN   = smem + s1 * STAGE;
        float* linsN = lins + s1 * 128;
        const uint32_t aA = sbase + s0 * STAGE;
        const int nb = wid * 8;

        float acc[2][4][4];
        #pragma unroll
        for (int mt = 0; mt < 2; ++mt)
            #pragma unroll
            for (int nt = 0; nt < 4; ++nt)
                #pragma unroll
                for (int r = 0; r < 4; ++r) acc[mt][nt][r] = 0.f;

        // deep-pipelined interleave: two chunk buffers in flight
        if (has_next) { LOAD_CHUNK(xa, n0n, nb + 0); LOAD_CHUNK(xb, n0n, nb + 2); }
        MMA_K2(aA, 0);
        MMA_K2(aA, 32);
        if (has_next) { CONV_CHUNK(xa, AhN, linsN, nb + 0); LOAD_CHUNK(xa, n0n, nb + 4); }
        MMA_K2(aA, 64);
        MMA_K2(aA, 96);
        if (has_next) { CONV_CHUNK(xb, AhN, linsN, nb + 2); LOAD_CHUNK(xb, n0n, nb + 6); }

        // epilogue: relu + W2 contraction inside fragments
        float rp[2][2];
        rp[0][0] = rp[0][1] = rp[1][0] = rp[1][1] = 0.f;
        #pragma unroll
        for (int mt = 0; mt < 2; ++mt)
            #pragma unroll
            for (int nt = 0; nt < 4; ++nt)
                #pragma unroll
                for (int r = 0; r < 4; ++r) {
                    int col = wn * 32 + nt * 8 + tig * 2 + (r & 1);
                    float hv = acc[mt][nt][r] + b1s[col];
                    rp[mt][r >> 1] = fmaf(fmaxf(hv, 0.f), w2s[col], rp[mt][r >> 1]);
                }
        float* psI = ps + (it & 1) * 512;
        #pragma unroll
        for (int mt = 0; mt < 2; ++mt)
            #pragma unroll
            for (int h = 0; h < 2; ++h) {
                float sum = rp[mt][h];
                sum += __shfl_xor_sync(0xffffffffu, sum, 1);
                sum += __shfl_xor_sync(0xffffffffu, sum, 2);
                if (tig == 0)
                    psI[(wm * 32 + mt * 16 + gid + h * 8) * 4 + wn] = sum;
            }

        if (has_next) { CONV_CHUNK(xa, AhN, linsN, nb + 4); CONV_CHUNK(xb, AhN, linsN, nb + 6); }
        __syncthreads();                     // stage s1 full, psI ready

        if (tid < 128) {
            const float* linsS0 = lins + s0 * 128;
            g_v[n0 + tid] = linsS0[tid] + psI[tid * 4] + psI[tid * 4 + 1]
                          + psI[tid * 4 + 2] + psI[tid * 4 + 3] + cst;
        }
    }

    #undef LOAD_CHUNK
    #undef CONV_CHUNK
    #undef MMA_K2
}

// ---------------------------------------------------------------------------
// Kernel 2: warp-per-segment aggregation; adaptive sort size
// ---------------------------------------------------------------------------
#define CAP 1024

template<int NR>
__device__ __forceinline__ void bsort(float* v, int lane)
{
    const int N = NR * 32;
    #pragma unroll
    for (int k = 2; k <= N; k <<= 1) {
        #pragma unroll
        for (int j = k >> 1; j > 0; j >>= 1) {
            if (j >= 32) {
                const int jr = j >> 5;
                #pragma unroll
                for (int r = 0; r < NR; ++r) {
                    if ((r & jr) == 0) {
                        int rp = r | jr;
                        bool up = (((r * 32) & k) == 0);
                        float a = v[r], b = v[rp];
                        float lo = fminf(a, b), hi = fmaxf(a, b);
                        v[r]  = up ? lo : hi;
                        v[rp] = up ? hi : lo;
                    }
                }
            } else {
                #pragma unroll
                for (int r = 0; r < NR; ++r) {
                    float other = __shfl_xor_sync(0xffffffffu, v[r], j);
                    bool lower = (lane & j) == 0;
                    bool up = (k < 32) ? ((lane & k) == 0) : (((r * 32) & k) == 0);
                    v[r] = (up == lower) ? fminf(v[r], other) : fmaxf(v[r], other);
                }
            }
        }
    }
}

__global__ __launch_bounds__(128)
void k_agg(const float* __restrict__ Wm1,
           const float* __restrict__ bm1,
           const float* __restrict__ Wm2,
           const float* __restrict__ bm2,
           float* __restrict__ out)
{
    __shared__ float ssort[4][256];
    __shared__ float sv[CAP];
    __shared__ float red[128];
    __shared__ float aggd[12];
    __shared__ int   dlist[4];
    __shared__ int   dcount;

    const int tid  = threadIdx.x;
    const int lane = tid & 31;
    const int wid  = tid >> 5;
    const int seg  = blockIdx.x * 4 + wid;

    if (tid == 0) dcount = 0;

    // start the dependent chain (g_off -> g_v) first
    const int start = g_off[seg];
    const int cnt   = g_off[seg + 1] - start;

    // hoist MLP weights into registers (independent; overlaps the chain)
    float wm1r[12][4], bm1r[4], wm2r[4];
    #pragma unroll
    for (int hh = 0; hh < 4; ++hh) {
        int h = hh * 32 + lane;
        bm1r[hh] = bm1[h];
        wm2r[hh] = Wm2[h];
        #pragma unroll
        for (int i = 0; i < 12; ++i)
            wm1r[i][hh] = Wm1[i * H_DIM + h];
    }
    __syncthreads();

    bool done = false;
    float sum = 0.f;
    if (cnt > 256) {
        if (lane == 0) { int p = atomicAdd(&dcount, 1); dlist[p] = wid; }
    } else if (cnt <= 128) {
        float v[4];
        #pragma unroll
        for (int r = 0; r < 4; ++r) {
            int i = r * 32 + lane;
            float x = (i < cnt) ? g_v[start + i] : FLT_MAX;
            v[r] = x;
            if (i < cnt) sum += x;
        }
        #pragma unroll
        for (int d = 16; d > 0; d >>= 1) sum += __shfl_xor_sync(0xffffffffu, sum, d);
        bsort<4>(v, lane);
        #pragma unroll
        for (int r = 0; r < 4; ++r) ssort[wid][r * 32 + lane] = v[r];
        __syncwarp();
        done = true;
    } else {
        float v[8];
        #pragma unroll
        for (int r = 0; r < 8; ++r) {
            int i = r * 32 + lane;
            float x = (i < cnt) ? g_v[start + i] : FLT_MAX;
            v[r] = x;
            if (i < cnt) sum += x;
        }
        #pragma unroll
        for (int d = 16; d > 0; d >>= 1) sum += __shfl_xor_sync(0xffffffffu, sum, d);
        bsort<8>(v, lane);
        #pragma unroll
        for (int r = 0; r < 8; ++r) ssort[wid][r * 32 + lane] = v[r];
        __syncwarp();
        done = true;
    }

    if (done) {
        float agg[12];
        if (cnt > 0) {
            const float* sw = ssort[wid];
            agg[0] = sum / (float)cnt;
            agg[1] = sw[cnt - 1];
            agg[2] = sw[0];
            #pragma unroll
            for (int qi = 0; qi < 9; ++qi) {
                float q    = (float)(qi + 1) * 0.1f;
                float pos  = q * (float)(cnt - 1);
                float f    = floorf(pos);
                float frac = pos - f;
                int lo = (int)f;
                if (lo > cnt - 1) lo = cnt - 1;
                if (lo < 0) lo = 0;
                int hi = lo + 1;
                if (hi > cnt - 1) hi = cnt - 1;
                agg[3 + qi] = sw[lo] + frac * (sw[hi] - sw[lo]);
            }
        } else {
            #pragma unroll
            for (int i = 0; i < 12; ++i) agg[i] = 0.f;
        }

        float c = 0.f;
        #pragma unroll
        for (int hh = 0; hh < 4; ++hh) {
            float hj = bm1r[hh];
            #pragma unroll
            for (int i = 0; i < 12; ++i)
                hj = fmaf(agg[i], wm1r[i][hh], hj);
            c = fmaf(fmaxf(hj, 0.f), wm2r[hh], c);
        }
        #pragma unroll
        for (int d = 16; d > 0; d >>= 1) c += __shfl_xor_sync(0xffffffffu, c, d);
        if (lane == 0) out[seg] = c + bm2[0];
    }
    __syncthreads();

    // ---- deferred (cnt > 256) segments: block-wide bitonic path ----
    for (int d = 0; d < dcount; ++d) {
        const int dseg   = blockIdx.x * 4 + dlist[d];
        const int dstart = g_off[dseg];
        const int dcnt   = g_off[dseg + 1] - dstart;

        int m = 1;
        while (m < dcnt) m <<= 1;
        if (m > CAP) m = CAP;

        for (int i = tid; i < m; i += 128)
            sv[i] = (i < dcnt && i < CAP) ? g_v[dstart + i] : FLT_MAX;
        __syncthreads();

        for (int ksz = 2; ksz <= m; ksz <<= 1) {
            for (int j = ksz >> 1; j > 0; j >>= 1) {
                for (int i = tid; i < m; i += 128) {
                    int p = i ^ j;
                    if (p > i) {
                        bool up = ((i & ksz) == 0);
                        float x = sv[i], y = sv[p];
                        if (up ? (x > y) : (x < y)) { sv[i] = y; sv[p] = x; }
                    }
                }
                __syncthreads();
            }
        }

        float ls = 0.f;
        for (int i = tid; i < dcnt; i += 128) ls += sv[i];
        red[tid] = ls;
        __syncthreads();
        for (int s = 64; s > 0; s >>= 1) {
            if (tid < s) red[tid] += red[tid + s];
            __syncthreads();
        }
        if (tid == 0) aggd[0] = red[0] / (float)dcnt;
        if (tid == 1) aggd[1] = sv[dcnt - 1];
        if (tid == 2) aggd[2] = sv[0];
        if (tid < 9) {
            float q    = (float)(tid + 1) * 0.1f;
            float pos  = q * (float)(dcnt - 1);
            float f    = floorf(pos);
            float frac = pos - f;
            int lo = (int)f;
            if (lo > dcnt - 1) lo = dcnt - 1;
            if (lo < 0) lo = 0;
            int hi = lo + 1;
            if (hi > dcnt - 1) hi = dcnt - 1;
            aggd[3 + tid] = sv[lo] + frac * (sv[hi] - sv[lo]);
        }
        __syncthreads();

        float contrib = 0.f;
        if (tid < H_DIM) {
            float hj = bm1[tid];
            #pragma unroll
            for (int i = 0; i < 12; ++i)
                hj = fmaf(aggd[i], Wm1[i * H_DIM + tid], hj);
            hj = fmaxf(hj, 0.f);
            contrib = hj * Wm2[tid];
        }
        red[tid] = contrib;
        __syncthreads();
        for (int s = 64; s > 0; s >>= 1) {
            if (tid < s) red[tid] += red[tid + s];
            __syncthreads();
        }
        if (tid == 0) out[dseg] = red[0] + bm2[0];
        __syncthreads();
    }
}

// ---------------------------------------------------------------------------
extern "C" void kernel_launch(void* const* d_in, const int* in_sizes, int n_in,
                              void* d_out, int out_size)
{
    const float4* emb4   = (const float4*)d_in[0];
    const int*    batch  = (const int*)  d_in[1];
    const float*  W_lins = (const float*)d_in[2];
    const float*  b_lins = (const float*)d_in[3];
    const float*  W1     = (const float*)d_in[4];
    const float*  b1     = (const float*)d_in[5];
    const float*  W2     = (const float*)d_in[6];
    const float*  b2     = (const float*)d_in[7];
    const float*  Wm1    = (const float*)d_in[8];
    const float*  bm1    = (const float*)d_in[9];
    const float*  Wm2    = (const float*)d_in[10];
    const float*  bm2    = (const float*)d_in[11];
    float* out = (float*)d_out;

    static int nsm = 0;
    if (nsm == 0) {
        cudaDeviceGetAttribute(&nsm, cudaDevAttrMultiProcessorCount, 0);
        if (nsm <= 0) nsm = 148;
        cudaFuncSetAttribute(k_node, cudaFuncAttributeMaxDynamicSharedMemorySize, SMEM_K1);
    }

    k_node<<<nsm, 512, SMEM_K1>>>(emb4, batch, W_lins, b_lins, W1, b1, W2, b2);
    k_agg<<<B_SEG / 4, 128>>>(Wm1, bm1, Wm2, bm2, out);
}

// round 16
// speedup vs baseline: 1.0628x; 1.0628x over previous
#include <cuda_runtime.h>
#include <cuda_fp16.h>
#include <float.h>
#include <math.h>
#include <cstdint>

#define N_NODES 131072
#define B_SEG   1024
#define H_DIM   128
#define TILE_N  128
#define NTILES  (N_NODES / TILE_N)

// Tiles: [128 rows][136 halves] -> 272 B row stride (16B-aligned, 17x16B units)
#define A_STRIDE 136
#define B_STRIDE 136

__device__ float g_v[N_NODES];
__device__ int   g_off[B_SEG + 1];

// ---- k_node smem layout (bytes) ----
static constexpr int STAGE    = 34816;                    // A fp16 tile per stage (x2)
static constexpr int SM_B     = 2 * STAGE;                // 69632
static constexpr int RAW_OFF  = SM_B + 34816;             // 104448
static constexpr int RAW_SIZE = 16 * 3 * 2048;            // 98304 (16 warps x 3 slots x 2KB)
static constexpr int SM_FLT   = RAW_OFF + RAW_SIZE;       // 202752
// floats: lins[3][128]=384, ps[2][128][4]=1024 -> 1408 floats
static constexpr int SMEM_K1  = SM_FLT + 1408 * 4;        // 208384

// ---------------------------------------------------------------------------
__device__ __forceinline__ uint32_t smem_u32(const void* p) {
    uint32_t a;
    asm("{ .reg .u64 t; cvta.to.shared.u64 t, %1; cvt.u32.u64 %0, t; }"
        : "=r"(a) : "l"(p));
    return a;
}
__device__ __forceinline__ void ldsm_x4(uint32_t* r, uint32_t a) {
    asm volatile("ldmatrix.sync.aligned.m8n8.x4.shared.b16 {%0,%1,%2,%3}, [%4];"
                 : "=r"(r[0]), "=r"(r[1]), "=r"(r[2]), "=r"(r[3]) : "r"(a));
}
__device__ __forceinline__ void ldsm_x2t(uint32_t* r, uint32_t a) {
    asm volatile("ldmatrix.sync.aligned.m8n8.x2.trans.shared.b16 {%0,%1}, [%2];"
                 : "=r"(r[0]), "=r"(r[1]) : "r"(a));
}
__device__ __forceinline__ void mma16816(float* d, const uint32_t* a, const uint32_t* b) {
    asm volatile(
        "mma.sync.aligned.m16n8k16.row.col.f32.f16.f16.f32 "
        "{%0,%1,%2,%3}, {%4,%5,%6,%7}, {%8,%9}, {%0,%1,%2,%3};"
        : "+f"(d[0]), "+f"(d[1]), "+f"(d[2]), "+f"(d[3])
        : "r"(a[0]), "r"(a[1]), "r"(a[2]), "r"(a[3]), "r"(b[0]), "r"(b[1]));
}

// ---------------------------------------------------------------------------
// Kernel 1: persistent pipelined node readout; cp.async raw staging
// ---------------------------------------------------------------------------
__global__ __launch_bounds__(512, 1)
void k_node(const float4* __restrict__ emb4,
            const int*    __restrict__ batch,
            const float*  __restrict__ W_lins,
            const float*  __restrict__ b_lins,
            const float*  __restrict__ W1,
            const float*  __restrict__ b1,
            const float*  __restrict__ W2,
            const float*  __restrict__ b2)
{
    extern __shared__ __align__(16) char smem[];
    float* lins = (float*)(smem + SM_FLT);   // [3][128]
    float* ps   = lins + 3 * 128;            // [2][128][4]

    const int tid  = threadIdx.x;
    const int lane = tid & 31;
    const int wid  = tid >> 5;
    const uint32_t sbase = smem_u32(smem);

    // ---- prelude: segment-offset scatter (batch sorted) ----
    for (int i = blockIdx.x * 512 + tid; i < N_NODES; i += gridDim.x * 512) {
        int b    = batch[i];
        int prev = (i == 0) ? -1 : batch[i - 1];
        for (int bb = prev + 1; bb <= b; ++bb) g_off[bb] = i;
        if (i == N_NODES - 1)
            for (int bb = b + 1; bb <= B_SEG; ++bb) g_off[bb] = N_NODES;
    }

    // one-time staging: W1 -> fp16 B tile
    {
        char* Bh = smem + SM_B;
        for (int i = tid; i < 128 * 128 / 4; i += 512) {
            float4 w = ((const float4*)W1)[i];
            int c  = i >> 5;
            int h4 = (i & 31) * 4;
            int off = (c * B_STRIDE + h4) * 2;
            *(__half2*)(Bh + off)     = __floats2half2_rn(w.x, w.y);
            *(__half2*)(Bh + off + 4) = __floats2half2_rn(w.z, w.w);
        }
    }

    // per-lane constants
    float wlr[3][4];
    #pragma unroll
    for (int r = 0; r < 3; ++r)
        #pragma unroll
        for (int cc = 0; cc < 4; ++cc)
            wlr[r][cc] = W_lins[r * 128 + cc * 32 + lane];

    const int wm = wid >> 2;          // 0..3 -> rows wm*32
    const int wn = wid & 3;           // 0..3 -> cols wn*32
    const int lr = lane & 15;
    const int lk = (lane >> 4) * 8;
    const int gid = lane >> 2;
    const int tig = lane & 3;
    const int nb = wid * 8;           // warp's node base within tile

    float b1r[4][2], w2r[4][2];
    #pragma unroll
    for (int nt = 0; nt < 4; ++nt)
        #pragma unroll
        for (int j = 0; j < 2; ++j) {
            int col = wn * 32 + nt * 8 + tig * 2 + j;
            b1r[nt][j] = b1[col];
            w2r[nt][j] = W2[col];
        }
    const float cst = b_lins[0] + b_lins[1] + b_lins[2] + b2[0];

    const uint32_t aB = sbase + SM_B;
    const uint32_t rawbase = sbase + RAW_OFF + wid * 3 * 2048;

    // ---- cp.async helpers (warp-self-contained: each lane copies what it reads) ----
    #define ISSUE_NODE(n0_, j_)                                              \
        do {                                                                 \
            uint32_t dst_ = rawbase + ((j_) % 3) * 2048 + lane * 16;         \
            const float4* src_ = emb4 + (size_t)((n0_) + nb + (j_)) * 128 + lane; \
            asm volatile("cp.async.cg.shared.global [%0], [%1], 16;"         \
                         :: "r"(dst_), "l"(src_) : "memory");                \
            asm volatile("cp.async.cg.shared.global [%0], [%1], 16;"         \
                         :: "r"(dst_ + 512), "l"(src_ + 32) : "memory");     \
            asm volatile("cp.async.cg.shared.global [%0], [%1], 16;"         \
                         :: "r"(dst_ + 1024), "l"(src_ + 64) : "memory");    \
            asm volatile("cp.async.cg.shared.global [%0], [%1], 16;"         \
                         :: "r"(dst_ + 1536), "l"(src_ + 96) : "memory");    \
            asm volatile("cp.async.commit_group;" ::: "memory");             \
        } while (0)

    #define WAITG(N_) asm volatile("cp.async.wait_group %0;" :: "n"(N_) : "memory")

    #define CONV_NODE(j_, AhS_, linsS_)                                      \
        do {                                                                 \
            const float4* rp_ = (const float4*)(smem + RAW_OFF               \
                                + (wid * 3 + ((j_) % 3)) * 2048);            \
            float l_ = 0.f;                                                  \
            _Pragma("unroll")                                                \
            for (int cc_ = 0; cc_ < 4; ++cc_) {                              \
                float4 xx_ = rp_[cc_ * 32 + lane];                           \
                int c_ = cc_ * 32 + lane;                                    \
                l_ = fmaf(xx_.x, wlr[0][cc_], l_);                           \
                l_ = fmaf(xx_.y, wlr[1][cc_], l_);                           \
                l_ = fmaf(xx_.z, wlr[2][cc_], l_);                           \
                *(__half*)((AhS_) + ((nb + (j_)) * A_STRIDE + c_) * 2) =     \
                    __float2half_rn(xx_.w);                                  \
            }                                                                \
            _Pragma("unroll")                                                \
            for (int d_ = 16; d_ > 0; d_ >>= 1)                              \
                l_ += __shfl_xor_sync(0xffffffffu, l_, d_);                  \
            if (lane == 0) (linsS_)[nb + (j_)] = l_;                         \
        } while (0)

    #define MMA_K2(aA_, k0base_)                                             \
        do {                                                                 \
            _Pragma("unroll")                                                \
            for (int kk_ = 0; kk_ < 2; ++kk_) {                              \
                int k0_ = (k0base_) + kk_ * 16;                              \
                uint32_t bh_[4][2];                                          \
                _Pragma("unroll")                                            \
                for (int nt_ = 0; nt_ < 4; ++nt_) {                          \
                    uint32_t boff_ = (uint32_t)(((k0_ + lr) * B_STRIDE + wn * 32 + nt_ * 8) * 2); \
                    ldsm_x2t(bh_[nt_], aB + boff_);                          \
                }                                                            \
                _Pragma("unroll")                                            \
                for (int mt_ = 0; mt_ < 2; ++mt_) {                          \
                    uint32_t aoff_ = (uint32_t)(((wm * 32 + mt_ * 16 + lr) * A_STRIDE + k0_ + lk) * 2); \
                    uint32_t ah_[4];                                         \
                    ldsm_x4(ah_, (aA_) + aoff_);                             \
                    _Pragma("unroll")                                        \
                    for (int nt_ = 0; nt_ < 4; ++nt_)                        \
                        mma16816(acc[mt_][nt_], ah_, bh_[nt_]);              \
                }                                                            \
            }                                                                \
        } while (0)

    __syncthreads();

    // ---- prologue: load tile t0 into A stage 0 via plain register loads ----
    int t = blockIdx.x;
    if (t < NTILES) {
        char*  Ah0   = smem;
        float* lins0 = lins;
        const int n0p = t * TILE_N;
        #pragma unroll 1
        for (int j = 0; j < 8; ++j) {
            const float4* p = emb4 + (size_t)(n0p + nb + j) * 128 + lane;
            float4 x0 = p[0], x1 = p[32], x2 = p[64], x3 = p[96];
            float l = 0.f;
            l = fmaf(x0.x, wlr[0][0], l); l = fmaf(x0.y, wlr[1][0], l); l = fmaf(x0.z, wlr[2][0], l);
            l = fmaf(x1.x, wlr[0][1], l); l = fmaf(x1.y, wlr[1][1], l); l = fmaf(x1.z, wlr[2][1], l);
            l = fmaf(x2.x, wlr[0][2], l); l = fmaf(x2.y, wlr[1][2], l); l = fmaf(x2.z, wlr[2][2], l);
            l = fmaf(x3.x, wlr[0][3], l); l = fmaf(x3.y, wlr[1][3], l); l = fmaf(x3.z, wlr[2][3], l);
            int row = (nb + j) * A_STRIDE;
            *(__half*)(Ah0 + (row + lane) * 2)       = __float2half_rn(x0.w);
            *(__half*)(Ah0 + (row + 32 + lane) * 2)  = __float2half_rn(x1.w);
            *(__half*)(Ah0 + (row + 64 + lane) * 2)  = __float2half_rn(x2.w);
            *(__half*)(Ah0 + (row + 96 + lane) * 2)  = __float2half_rn(x3.w);
            #pragma unroll
            for (int d = 16; d > 0; d >>= 1)
                l += __shfl_xor_sync(0xffffffffu, l, d);
            if (lane == 0) lins0[nb + j] = l;
        }
    }
    __syncthreads();

    int it = 0;
    for (; t < NTILES; t += gridDim.x, ++it) {
        const int s0 = it & 1;
        const int n0 = t * TILE_N;
        const int tn = t + gridDim.x;
        const bool has_next = (tn < NTILES);
        const int n0n = tn * TILE_N;

        char*  AhN   = smem + (s0 ^ 1) * STAGE;
        float* linsC = lins + (it % 3) * 128;         // current tile's lin
        float* linsN = lins + ((it + 1) % 3) * 128;   // next tile's lin
        const uint32_t aA = sbase + s0 * STAGE;

        float acc[2][4][4];
        #pragma unroll
        for (int mt = 0; mt < 2; ++mt)
            #pragma unroll
            for (int nt = 0; nt < 4; ++nt)
                #pragma unroll
                for (int r = 0; r < 4; ++r) acc[mt][nt][r] = 0.f;

        // cp.async-pipelined: 3 node-groups in flight per warp at all times
        if (has_next) { ISSUE_NODE(n0n, 0); ISSUE_NODE(n0n, 1); ISSUE_NODE(n0n, 2); }
        MMA_K2(aA, 0);
        if (has_next) {
            WAITG(2); CONV_NODE(0, AhN, linsN); ISSUE_NODE(n0n, 3);
            WAITG(2); CONV_NODE(1, AhN, linsN); ISSUE_NODE(n0n, 4);
        }
        MMA_K2(aA, 32);
        if (has_next) {
            WAITG(2); CONV_NODE(2, AhN, linsN); ISSUE_NODE(n0n, 5);
            WAITG(2); CONV_NODE(3, AhN, linsN); ISSUE_NODE(n0n, 6);
        }
        MMA_K2(aA, 64);
        if (has_next) {
            WAITG(2); CONV_NODE(4, AhN, linsN); ISSUE_NODE(n0n, 7);
            WAITG(2); CONV_NODE(5, AhN, linsN);
        }
        MMA_K2(aA, 96);
        if (has_next) {
            WAITG(1); CONV_NODE(6, AhN, linsN);
            WAITG(0); CONV_NODE(7, AhN, linsN);
        }

        // epilogue: relu + W2 contraction inside fragments
        float rp[2][2];
        rp[0][0] = rp[0][1] = rp[1][0] = rp[1][1] = 0.f;
        #pragma unroll
        for (int mt = 0; mt < 2; ++mt)
            #pragma unroll
            for (int nt = 0; nt < 4; ++nt)
                #pragma unroll
                for (int r = 0; r < 4; ++r) {
                    float hv = acc[mt][nt][r] + b1r[nt][r & 1];
                    rp[mt][r >> 1] = fmaf(fmaxf(hv, 0.f), w2r[nt][r & 1], rp[mt][r >> 1]);
                }
        float* psI = ps + (it & 1) * 512;
        #pragma unroll
        for (int mt = 0; mt < 2; ++mt)
            #pragma unroll
            for (int h = 0; h < 2; ++h) {
                float sum = rp[mt][h];
                sum += __shfl_xor_sync(0xffffffffu, sum, 1);
                sum += __shfl_xor_sync(0xffffffffu, sum, 2);
                if (tig == 0)
                    psI[(wm * 32 + mt * 16 + gid + h * 8) * 4 + wn] = sum;
            }
        __syncthreads();                     // A stage s0^1 full, psI ready

        if (tid < 128) {
            g_v[n0 + tid] = linsC[tid] + psI[tid * 4] + psI[tid * 4 + 1]
                          + psI[tid * 4 + 2] + psI[tid * 4 + 3] + cst;
        }
    }

    #undef ISSUE_NODE
    #undef WAITG
    #undef CONV_NODE
    #undef MMA_K2
}

// ---------------------------------------------------------------------------
// Kernel 2: warp-per-segment aggregation; adaptive sort size
// ---------------------------------------------------------------------------
#define CAP 1024

template<int NR>
__device__ __forceinline__ void bsort(float* v, int lane)
{
    const int N = NR * 32;
    #pragma unroll
    for (int k = 2; k <= N; k <<= 1) {
        #pragma unroll
        for (int j = k >> 1; j > 0; j >>= 1) {
            if (j >= 32) {
                const int jr = j >> 5;
                #pragma unroll
                for (int r = 0; r < NR; ++r) {
                    if ((r & jr) == 0) {
                        int rp = r | jr;
                        bool up = (((r * 32) & k) == 0);
                        float a = v[r], b = v[rp];
                        float lo = fminf(a, b), hi = fmaxf(a, b);
                        v[r]  = up ? lo : hi;
                        v[rp] = up ? hi : lo;
                    }
                }
            } else {
                #pragma unroll
                for (int r = 0; r < NR; ++r) {
                    float other = __shfl_xor_sync(0xffffffffu, v[r], j);
                    bool lower = (lane & j) == 0;
                    bool up = (k < 32) ? ((lane & k) == 0) : (((r * 32) & k) == 0);
                    v[r] = (up == lower) ? fminf(v[r], other) : fmaxf(v[r], other);
                }
            }
        }
    }
}

__global__ __launch_bounds__(128)
void k_agg(const float* __restrict__ Wm1,
           const float* __restrict__ bm1,
           const float* __restrict__ Wm2,
           const float* __restrict__ bm2,
           float* __restrict__ out)
{
    __shared__ float ssort[4][256];
    __shared__ float sv[CAP];
    __shared__ float red[128];
    __shared__ float aggd[12];
    __shared__ int   dlist[4];
    __shared__ int   dcount;

    const int tid  = threadIdx.x;
    const int lane = tid & 31;
    const int wid  = tid >> 5;
    const int seg  = blockIdx.x * 4 + wid;

    if (tid == 0) dcount = 0;

    // start the dependent chain (g_off -> g_v) first
    const int start = g_off[seg];
    const int cnt   = g_off[seg + 1] - start;

    // hoist MLP weights into registers (independent; overlaps the chain)
    float wm1r[12][4], bm1r[4], wm2r[4];
    #pragma unroll
    for (int hh = 0; hh < 4; ++hh) {
        int h = hh * 32 + lane;
        bm1r[hh] = bm1[h];
        wm2r[hh] = Wm2[h];
        #pragma unroll
        for (int i = 0; i < 12; ++i)
            wm1r[i][hh] = Wm1[i * H_DIM + h];
    }
    __syncthreads();

    bool done = false;
    float sum = 0.f;
    if (cnt > 256) {
        if (lane == 0) { int p = atomicAdd(&dcount, 1); dlist[p] = wid; }
    } else if (cnt <= 128) {
        float v[4];
        #pragma unroll
        for (int r = 0; r < 4; ++r) {
            int i = r * 32 + lane;
            float x = (i < cnt) ? g_v[start + i] : FLT_MAX;
            v[r] = x;
            if (i < cnt) sum += x;
        }
        #pragma unroll
        for (int d = 16; d > 0; d >>= 1) sum += __shfl_xor_sync(0xffffffffu, sum, d);
        bsort<4>(v, lane);
        #pragma unroll
        for (int r = 0; r < 4; ++r) ssort[wid][r * 32 + lane] = v[r];
        __syncwarp();
        done = true;
    } else {
        float v[8];
        #pragma unroll
        for (int r = 0; r < 8; ++r) {
            int i = r * 32 + lane;
            float x = (i < cnt) ? g_v[start + i] : FLT_MAX;
            v[r] = x;
            if (i < cnt) sum += x;
        }
        #pragma unroll
        for (int d = 16; d > 0; d >>= 1) sum += __shfl_xor_sync(0xffffffffu, sum, d);
        bsort<8>(v, lane);
        #pragma unroll
        for (int r = 0; r < 8; ++r) ssort[wid][r * 32 + lane] = v[r];
        __syncwarp();
        done = true;
    }

    if (done) {
        float agg[12];
        if (cnt > 0) {
            const float* sw = ssort[wid];
            agg[0] = sum / (float)cnt;
            agg[1] = sw[cnt - 1];
            agg[2] = sw[0];
            #pragma unroll
            for (int qi = 0; qi < 9; ++qi) {
                float q    = (float)(qi + 1) * 0.1f;
                float pos  = q * (float)(cnt - 1);
                float f    = floorf(pos);
                float frac = pos - f;
                int lo = (int)f;
                if (lo > cnt - 1) lo = cnt - 1;
                if (lo < 0) lo = 0;
                int hi = lo + 1;
                if (hi > cnt - 1) hi = cnt - 1;
                agg[3 + qi] = sw[lo] + frac * (sw[hi] - sw[lo]);
            }
        } else {
            #pragma unroll
            for (int i = 0; i < 12; ++i) agg[i] = 0.f;
        }

        float c = 0.f;
        #pragma unroll
        for (int hh = 0; hh < 4; ++hh) {
            float hj = bm1r[hh];
            #pragma unroll
            for (int i = 0; i < 12; ++i)
                hj = fmaf(agg[i], wm1r[i][hh], hj);
            c = fmaf(fmaxf(hj, 0.f), wm2r[hh], c);
        }
        #pragma unroll
        for (int d = 16; d > 0; d >>= 1) c += __shfl_xor_sync(0xffffffffu, c, d);
        if (lane == 0) out[seg] = c + bm2[0];
    }
    __syncthreads();

    // ---- deferred (cnt > 256) segments: block-wide bitonic path ----
    for (int d = 0; d < dcount; ++d) {
        const int dseg   = blockIdx.x * 4 + dlist[d];
        const int dstart = g_off[dseg];
        const int dcnt   = g_off[dseg + 1] - dstart;

        int m = 1;
        while (m < dcnt) m <<= 1;
        if (m > CAP) m = CAP;

        for (int i = tid; i < m; i += 128)
            sv[i] = (i < dcnt && i < CAP) ? g_v[dstart + i] : FLT_MAX;
        __syncthreads();

        for (int ksz = 2; ksz <= m; ksz <<= 1) {
            for (int j = ksz >> 1; j > 0; j >>= 1) {
                for (int i = tid; i < m; i += 128) {
                    int p = i ^ j;
                    if (p > i) {
                        bool up = ((i & ksz) == 0);
                        float x = sv[i], y = sv[p];
                        if (up ? (x > y) : (x < y)) { sv[i] = y; sv[p] = x; }
                    }
                }
                __syncthreads();
            }
        }

        float ls = 0.f;
        for (int i = tid; i < dcnt; i += 128) ls += sv[i];
        red[tid] = ls;
        __syncthreads();
        for (int s = 64; s > 0; s >>= 1) {
            if (tid < s) red[tid] += red[tid + s];
            __syncthreads();
        }
        if (tid == 0) aggd[0] = red[0] / (float)dcnt;
        if (tid == 1) aggd[1] = sv[dcnt - 1];
        if (tid == 2) aggd[2] = sv[0];
        if (tid < 9) {
            float q    = (float)(tid + 1) * 0.1f;
            float pos  = q * (float)(dcnt - 1);
            float f    = floorf(pos);
            float frac = pos - f;
            int lo = (int)f;
            if (lo > dcnt - 1) lo = dcnt - 1;
            if (lo < 0) lo = 0;
            int hi = lo + 1;
            if (hi > dcnt - 1) hi = dcnt - 1;
            aggd[3 + tid] = sv[lo] + frac * (sv[hi] - sv[lo]);
        }
        __syncthreads();

        float contrib = 0.f;
        if (tid < H_DIM) {
            float hj = bm1[tid];
            #pragma unroll
            for (int i = 0; i < 12; ++i)
                hj = fmaf(aggd[i], Wm1[i * H_DIM + tid], hj);
            hj = fmaxf(hj, 0.f);
            contrib = hj * Wm2[tid];
        }
        red[tid] = contrib;
        __syncthreads();
        for (int s = 64; s > 0; s >>= 1) {
            if (tid < s) red[tid] += red[tid + s];
            __syncthreads();
        }
        if (tid == 0) out[dseg] = red[0] + bm2[0];
        __syncthreads();
    }
}

// ---------------------------------------------------------------------------
extern "C" void kernel_launch(void* const* d_in, const int* in_sizes, int n_in,
                              void* d_out, int out_size)
{
    const float4* emb4   = (const float4*)d_in[0];
    const int*    batch  = (const int*)  d_in[1];
    const float*  W_lins = (const float*)d_in[2];
    const float*  b_lins = (const float*)d_in[3];
    const float*  W1     = (const float*)d_in[4];
    const float*  b1     = (const float*)d_in[5];
    const float*  W2     = (const float*)d_in[6];
    const float*  b2     = (const float*)d_in[7];
    const float*  Wm1    = (const float*)d_in[8];
    const float*  bm1    = (const float*)d_in[9];
    const float*  Wm2    = (const float*)d_in[10];
    const float*  bm2    = (const float*)d_in[11];
    float* out = (float*)d_out;

    static int nsm = 0;
    if (nsm == 0) {
        cudaDeviceGetAttribute(&nsm, cudaDevAttrMultiProcessorCount, 0);
        if (nsm <= 0) nsm = 148;
        cudaFuncSetAttribute(k_node, cudaFuncAttributeMaxDynamicSharedMemorySize, SMEM_K1);
    }

    k_node<<<nsm, 512, SMEM_K1>>>(emb4, batch, W_lins, b_lins, W1, b1, W2, b2);
    k_agg<<<B_SEG / 4, 128>>>(Wm1, bm1, Wm2, bm2, out);
}

// round 17
// speedup vs baseline: 1.0876x; 1.0234x over previous
#include <cuda_runtime.h>
#include <cuda_fp16.h>
#include <float.h>
#include <math.h>
#include <cstdint>

#define N_NODES 131072
#define B_SEG   1024
#define H_DIM   128
#define TILE_N  128
#define NTILES  (N_NODES / TILE_N)
#define NSTAGES 3

// Tiles: [128 rows][136 halves] -> 272 B row stride (16B-aligned, 17x16B units)
#define A_STRIDE 136
#define B_STRIDE 136

__device__ float    g_v[N_NODES];
__device__ int      g_off[B_SEG + 1];
__device__ unsigned g_barrier = 0;

// ---- smem layout (bytes) ----
static constexpr int STAGE   = 34816;                   // A fp16 tile per stage
static constexpr int SM_B    = NSTAGES * STAGE;         // 104448
static constexpr int SM_FLT  = SM_B + 34816;            // 139264
// floats: lins[3][128]=384, ps[2][128][4]=1024 -> 1408 floats
static constexpr int SMEM_K1 = SM_FLT + 1408 * 4;       // 144896
// agg-phase reuse (post-barrier): ssort[16][256] at 0 (16KB, inside stage0),
// sv[1024] at STAGE, red[512] at STAGE+4096, scalars after.

// ---------------------------------------------------------------------------
__device__ __forceinline__ uint32_t smem_u32(const void* p) {
    uint32_t a;
    asm("{ .reg .u64 t; cvta.to.shared.u64 t, %1; cvt.u32.u64 %0, t; }"
        : "=r"(a) : "l"(p));
    return a;
}
__device__ __forceinline__ void ldsm_x4(uint32_t* r, uint32_t a) {
    asm volatile("ldmatrix.sync.aligned.m8n8.x4.shared.b16 {%0,%1,%2,%3}, [%4];"
                 : "=r"(r[0]), "=r"(r[1]), "=r"(r[2]), "=r"(r[3]) : "r"(a));
}
__device__ __forceinline__ void ldsm_x2t(uint32_t* r, uint32_t a) {
    asm volatile("ldmatrix.sync.aligned.m8n8.x2.trans.shared.b16 {%0,%1}, [%2];"
                 : "=r"(r[0]), "=r"(r[1]) : "r"(a));
}
__device__ __forceinline__ void mma16816(float* d, const uint32_t* a, const uint32_t* b) {
    asm volatile(
        "mma.sync.aligned.m16n8k16.row.col.f32.f16.f16.f32 "
        "{%0,%1,%2,%3}, {%4,%5,%6,%7}, {%8,%9}, {%0,%1,%2,%3};"
        : "+f"(d[0]), "+f"(d[1]), "+f"(d[2]), "+f"(d[3])
        : "r"(a[0]), "r"(a[1]), "r"(a[2]), "r"(a[3]), "r"(b[0]), "r"(b[1]));
}

// ticket grid barrier: monotonic across graph replays (epoch = multiples of nb)
__device__ __forceinline__ void grid_sync(int nb) {
    __syncthreads();
    __threadfence();
    if (threadIdx.x == 0) {
        unsigned ticket = atomicAdd(&g_barrier, 1u) + 1u;
        unsigned target = ((ticket + (unsigned)nb - 1u) / (unsigned)nb) * (unsigned)nb;
        while (*(volatile unsigned*)&g_barrier < target) { }
    }
    __syncthreads();
    __threadfence();
}

// register bitonic sort of NR*32 elements (idx = r*32 + lane)
template<int NR>
__device__ __forceinline__ void bsort(float* v, int lane)
{
    const int N = NR * 32;
    #pragma unroll
    for (int k = 2; k <= N; k <<= 1) {
        #pragma unroll
        for (int j = k >> 1; j > 0; j >>= 1) {
            if (j >= 32) {
                const int jr = j >> 5;
                #pragma unroll
                for (int r = 0; r < NR; ++r) {
                    if ((r & jr) == 0) {
                        int rp = r | jr;
                        bool up = (((r * 32) & k) == 0);
                        float a = v[r], b = v[rp];
                        float lo = fminf(a, b), hi = fmaxf(a, b);
                        v[r]  = up ? lo : hi;
                        v[rp] = up ? hi : lo;
                    }
                }
            } else {
                #pragma unroll
                for (int r = 0; r < NR; ++r) {
                    float other = __shfl_xor_sync(0xffffffffu, v[r], j);
                    bool lower = (lane & j) == 0;
                    bool up = (k < 32) ? ((lane & k) == 0) : (((r * 32) & k) == 0);
                    v[r] = (up == lower) ? fminf(v[r], other) : fmaxf(v[r], other);
                }
            }
        }
    }
}

// ---------------------------------------------------------------------------
// Fused kernel: node readout (R13 pipeline) + grid barrier + segment agg
// ---------------------------------------------------------------------------
__global__ __launch_bounds__(512, 1)
void k_fused(const float4* __restrict__ emb4,
             const int*    __restrict__ batch,
             const float*  __restrict__ W_lins,
             const float*  __restrict__ b_lins,
             const float*  __restrict__ W1,
             const float*  __restrict__ b1,
             const float*  __restrict__ W2,
             const float*  __restrict__ b2,
             const float*  __restrict__ Wm1,
             const float*  __restrict__ bm1,
             const float*  __restrict__ Wm2,
             const float*  __restrict__ bm2,
             float* __restrict__ out)
{
    extern __shared__ __align__(16) char smem[];
    float* lins = (float*)(smem + SM_FLT);   // [3][128]
    float* ps   = lins + NSTAGES * 128;      // [2][128][4]

    const int tid  = threadIdx.x;
    const int lane = tid & 31;
    const int wid  = tid >> 5;
    const uint32_t sbase = smem_u32(smem);

    // ---- prelude: segment-offset scatter (batch sorted) ----
    for (int i = blockIdx.x * 512 + tid; i < N_NODES; i += gridDim.x * 512) {
        int b    = batch[i];
        int prev = (i == 0) ? -1 : batch[i - 1];
        for (int bb = prev + 1; bb <= b; ++bb) g_off[bb] = i;
        if (i == N_NODES - 1)
            for (int bb = b + 1; bb <= B_SEG; ++bb) g_off[bb] = N_NODES;
    }

    // one-time staging: W1 -> fp16 B tile
    {
        char* Bh = smem + SM_B;
        for (int i = tid; i < 128 * 128 / 4; i += 512) {
            float4 w = ((const float4*)W1)[i];
            int c  = i >> 5;
            int h4 = (i & 31) * 4;
            int off = (c * B_STRIDE + h4) * 2;
            *(__half2*)(Bh + off)     = __floats2half2_rn(w.x, w.y);
            *(__half2*)(Bh + off + 4) = __floats2half2_rn(w.z, w.w);
        }
    }

    // per-lane constants
    float wlr[3][4];
    #pragma unroll
    for (int r = 0; r < 3; ++r)
        #pragma unroll
        for (int cc = 0; cc < 4; ++cc)
            wlr[r][cc] = W_lins[r * 128 + cc * 32 + lane];

    const int wm = wid >> 2;          // 0..3 -> rows wm*32
    const int wn = wid & 3;           // 0..3 -> cols wn*32
    const int lr = lane & 15;
    const int lk = (lane >> 4) * 8;
    const int gid = lane >> 2;
    const int tig = lane & 3;

    float b1r[4][2], w2r[4][2];
    #pragma unroll
    for (int nt = 0; nt < 4; ++nt)
        #pragma unroll
        for (int j = 0; j < 2; ++j) {
            int col = wn * 32 + nt * 8 + tig * 2 + j;
            b1r[nt][j] = b1[col];
            w2r[nt][j] = W2[col];
        }
    const float cst = b_lins[0] + b_lins[1] + b_lins[2] + b2[0];

    const uint32_t aB = sbase + SM_B;
    float4 x[2][4];

    #define LOAD_CHUNK(n0_, nl_)                                             \
        do {                                                                 \
            _Pragma("unroll")                                                \
            for (int k_ = 0; k_ < 2; ++k_) {                                 \
                const float4* p_ = emb4 + (size_t)((n0_) + (nl_) + k_) * 128 + lane; \
                x[k_][0] = p_[0];                                            \
                x[k_][1] = p_[32];                                           \
                x[k_][2] = p_[64];                                           \
                x[k_][3] = p_[96];                                           \
            }                                                                \
        } while (0)

    #define CONV_CHUNK(AhS_, linsS_, nl_)                                    \
        do {                                                                 \
            _Pragma("unroll")                                                \
            for (int k_ = 0; k_ < 2; ++k_) {                                 \
                float l_ = 0.f;                                              \
                _Pragma("unroll")                                            \
                for (int cc_ = 0; cc_ < 4; ++cc_) {                          \
                    int c_ = cc_ * 32 + lane;                                \
                    l_ = fmaf(x[k_][cc_].x, wlr[0][cc_], l_);                \
                    l_ = fmaf(x[k_][cc_].y, wlr[1][cc_], l_);                \
                    l_ = fmaf(x[k_][cc_].z, wlr[2][cc_], l_);                \
                    *(__half*)((AhS_) + (((nl_) + k_) * A_STRIDE + c_) * 2) = \
                        __float2half_rn(x[k_][cc_].w);                       \
                }                                                            \
                _Pragma("unroll")                                            \
                for (int d_ = 16; d_ > 0; d_ >>= 1)                          \
                    l_ += __shfl_xor_sync(0xffffffffu, l_, d_);              \
                if (lane == 0) (linsS_)[(nl_) + k_] = l_;                    \
            }                                                                \
        } while (0)

    #define MMA_K2(aA_, k0base_)                                             \
        do {                                                                 \
            _Pragma("unroll")                                                \
            for (int kk_ = 0; kk_ < 2; ++kk_) {                              \
                int k0_ = (k0base_) + kk_ * 16;                              \
                uint32_t bh_[4][2];                                          \
                _Pragma("unroll")                                            \
                for (int nt_ = 0; nt_ < 4; ++nt_) {                          \
                    uint32_t boff_ = (uint32_t)(((k0_ + lr) * B_STRIDE + wn * 32 + nt_ * 8) * 2); \
                    ldsm_x2t(bh_[nt_], aB + boff_);                          \
                }                                                            \
                _Pragma("unroll")                                            \
                for (int mt_ = 0; mt_ < 2; ++mt_) {                          \
                    uint32_t aoff_ = (uint32_t)(((wm * 32 + mt_ * 16 + lr) * A_STRIDE + k0_ + lk) * 2); \
                    uint32_t ah_[4];                                         \
                    ldsm_x4(ah_, (aA_) + aoff_);                             \
                    _Pragma("unroll")                                        \
                    for (int nt_ = 0; nt_ < 4; ++nt_)                        \
                        mma16816(acc[mt_][nt_], ah_, bh_[nt_]);              \
                }                                                            \
            }                                                                \
        } while (0)

    __syncthreads();

    // ---- prologue: load tile t0 into stage 0 ----
    int t = blockIdx.x;
    if (t < NTILES) {
        char*  Ah0   = smem;
        float* lins0 = lins;
        const int n0p = t * TILE_N;
        #pragma unroll 1
        for (int ch = 0; ch < 4; ++ch) {
            int nl = wid * 8 + ch * 2;
            LOAD_CHUNK(n0p, nl);
            CONV_CHUNK(Ah0, lins0, nl);
        }
    }
    __syncthreads();

    int it = 0;
    for (; t < NTILES; t += gridDim.x, ++it) {
        const int s0 = it % NSTAGES;
        const int s1 = (it + 1) % NSTAGES;
        const int n0 = t * TILE_N;
        const int tn = t + gridDim.x;
        const bool has_next = (tn < NTILES);
        const int n0n = tn * TILE_N;

        char*  AhN   = smem + s1 * STAGE;
        float* linsN = lins + s1 * 128;
        const uint32_t aA = sbase + s0 * STAGE;
        const int nb = wid * 8;

        float acc[2][4][4];
        #pragma unroll
        for (int mt = 0; mt < 2; ++mt)
            #pragma unroll
            for (int nt = 0; nt < 4; ++nt)
                #pragma unroll
                for (int r = 0; r < 4; ++r) acc[mt][nt][r] = 0.f;

        // interleaved: prefetch chunks of tile t+1 while MMA'ing tile t
        if (has_next) LOAD_CHUNK(n0n, nb + 0);
        MMA_K2(aA, 0);
        if (has_next) { CONV_CHUNK(AhN, linsN, nb + 0); LOAD_CHUNK(n0n, nb + 2); }
        MMA_K2(aA, 32);
        if (has_next) { CONV_CHUNK(AhN, linsN, nb + 2); LOAD_CHUNK(n0n, nb + 4); }
        MMA_K2(aA, 64);
        if (has_next) { CONV_CHUNK(AhN, linsN, nb + 4); LOAD_CHUNK(n0n, nb + 6); }
        MMA_K2(aA, 96);
        if (has_next) CONV_CHUNK(AhN, linsN, nb + 6);

        // epilogue: relu + W2 contraction inside fragments
        float rp[2][2];
        rp[0][0] = rp[0][1] = rp[1][0] = rp[1][1] = 0.f;
        #pragma unroll
        for (int mt = 0; mt < 2; ++mt)
            #pragma unroll
            for (int nt = 0; nt < 4; ++nt)
                #pragma unroll
                for (int r = 0; r < 4; ++r) {
                    float hv = acc[mt][nt][r] + b1r[nt][r & 1];
                    rp[mt][r >> 1] = fmaf(fmaxf(hv, 0.f), w2r[nt][r & 1], rp[mt][r >> 1]);
                }
        float* psI = ps + (it & 1) * 512;
        #pragma unroll
        for (int mt = 0; mt < 2; ++mt)
            #pragma unroll
            for (int h = 0; h < 2; ++h) {
                float sum = rp[mt][h];
                sum += __shfl_xor_sync(0xffffffffu, sum, 1);
                sum += __shfl_xor_sync(0xffffffffu, sum, 2);
                if (tig == 0)
                    psI[(wm * 32 + mt * 16 + gid + h * 8) * 4 + wn] = sum;
            }
        __syncthreads();                     // stage s1 full, psI ready

        if (tid < 128) {
            const float* linsS0 = lins + s0 * 128;
            g_v[n0 + tid] = linsS0[tid] + psI[tid * 4] + psI[tid * 4 + 1]
                          + psI[tid * 4 + 2] + psI[tid * 4 + 3] + cst;
        }
    }

    #undef LOAD_CHUNK
    #undef CONV_CHUNK
    #undef MMA_K2

    // =======================================================================
    // GRID BARRIER, then segment aggregation phase (one warp per segment)
    // =======================================================================
    grid_sync(gridDim.x);

    float* ssortW = (float*)smem + wid * 256;            // in A stage 0
    float* sv     = (float*)(smem + STAGE);              // [1024]
    float* red    = (float*)(smem + STAGE + 4096);       // [512]
    float* aggd   = (float*)(smem + STAGE + 4096 + 2048);// [12]
    int*   dlist  = (int*)(aggd + 12);                   // [16]
    int*   dcnt_s = dlist + 16;

    if (tid == 0) *dcnt_s = 0;

    const int seg = blockIdx.x * 16 + wid;
    int start = 0, cnt = -1;
    if (seg < B_SEG) {
        start = g_off[seg];
        cnt   = g_off[seg + 1] - start;
    }

    // MLP weights to registers (independent of the g_v chain)
    float wm1r[12][4], bm1r[4], wm2r[4];
    #pragma unroll
    for (int hh = 0; hh < 4; ++hh) {
        int h = hh * 32 + lane;
        bm1r[hh] = bm1[h];
        wm2r[hh] = Wm2[h];
        #pragma unroll
        for (int i = 0; i < 12; ++i)
            wm1r[i][hh] = Wm1[i * H_DIM + h];
    }
    __syncthreads();

    if (seg < B_SEG) {
        bool deferred = false;
        float sum = 0.f;
        if (cnt > 256) {
            deferred = true;
            if (lane == 0) { int p = atomicAdd(dcnt_s, 1); dlist[p] = wid; }
        } else if (cnt <= 128) {
            float v[4];
            #pragma unroll
            for (int r = 0; r < 4; ++r) {
                int i = r * 32 + lane;
                float xx = (i < cnt) ? g_v[start + i] : FLT_MAX;
                v[r] = xx;
                if (i < cnt) sum += xx;
            }
            #pragma unroll
            for (int d = 16; d > 0; d >>= 1) sum += __shfl_xor_sync(0xffffffffu, sum, d);
            bsort<4>(v, lane);
            #pragma unroll
            for (int r = 0; r < 4; ++r) ssortW[r * 32 + lane] = v[r];
            __syncwarp();
        } else {
            float v[8];
            #pragma unroll
            for (int r = 0; r < 8; ++r) {
                int i = r * 32 + lane;
                float xx = (i < cnt) ? g_v[start + i] : FLT_MAX;
                v[r] = xx;
                if (i < cnt) sum += xx;
            }
            #pragma unroll
            for (int d = 16; d > 0; d >>= 1) sum += __shfl_xor_sync(0xffffffffu, sum, d);
            bsort<8>(v, lane);
            #pragma unroll
            for (int r = 0; r < 8; ++r) ssortW[r * 32 + lane] = v[r];
            __syncwarp();
        }

        if (!deferred) {
            float agg[12];
            if (cnt > 0) {
                agg[0] = sum / (float)cnt;
                agg[1] = ssortW[cnt - 1];
                agg[2] = ssortW[0];
                #pragma unroll
                for (int qi = 0; qi < 9; ++qi) {
                    float q    = (float)(qi + 1) * 0.1f;
                    float pos  = q * (float)(cnt - 1);
                    float f    = floorf(pos);
                    float frac = pos - f;
                    int lo = (int)f;
                    if (lo > cnt - 1) lo = cnt - 1;
                    if (lo < 0) lo = 0;
                    int hi = lo + 1;
                    if (hi > cnt - 1) hi = cnt - 1;
                    agg[3 + qi] = ssortW[lo] + frac * (ssortW[hi] - ssortW[lo]);
                }
            } else {
                #pragma unroll
                for (int i = 0; i < 12; ++i) agg[i] = 0.f;
            }

            float c = 0.f;
            #pragma unroll
            for (int hh = 0; hh < 4; ++hh) {
                float hj = bm1r[hh];
                #pragma unroll
                for (int i = 0; i < 12; ++i)
                    hj = fmaf(agg[i], wm1r[i][hh], hj);
                c = fmaf(fmaxf(hj, 0.f), wm2r[hh], c);
            }
            #pragma unroll
            for (int d = 16; d > 0; d >>= 1) c += __shfl_xor_sync(0xffffffffu, c, d);
            if (lane == 0) out[seg] = c + bm2[0];
        }
    }
    __syncthreads();

    // ---- deferred (cnt > 256) segments: block-wide bitonic path ----
    const int ndef = *dcnt_s;
    for (int d = 0; d < ndef; ++d) {
        const int dseg   = blockIdx.x * 16 + dlist[d];
        const int dstart = g_off[dseg];
        const int dc     = g_off[dseg + 1] - dstart;

        int m = 1;
        while (m < dc) m <<= 1;
        if (m > 1024) m = 1024;

        for (int i = tid; i < m; i += 512)
            sv[i] = (i < dc && i < 1024) ? g_v[dstart + i] : FLT_MAX;
        __syncthreads();

        for (int ksz = 2; ksz <= m; ksz <<= 1) {
            for (int j = ksz >> 1; j > 0; j >>= 1) {
                for (int i = tid; i < m; i += 512) {
                    int p = i ^ j;
                    if (p > i) {
                        bool up = ((i & ksz) == 0);
                        float xx = sv[i], y = sv[p];
                        if (up ? (xx > y) : (xx < y)) { sv[i] = y; sv[p] = xx; }
                    }
                }
                __syncthreads();
            }
        }

        float ls = 0.f;
        for (int i = tid; i < dc; i += 512) ls += sv[i];
        red[tid] = ls;
        __syncthreads();
        for (int s = 256; s > 0; s >>= 1) {
            if (tid < s) red[tid] += red[tid + s];
            __syncthreads();
        }
        if (tid == 0) aggd[0] = red[0] / (float)dc;
        if (tid == 1) aggd[1] = sv[dc - 1];
        if (tid == 2) aggd[2] = sv[0];
        if (tid < 9) {
            float q    = (float)(tid + 1) * 0.1f;
            float pos  = q * (float)(dc - 1);
            float f    = floorf(pos);
            float frac = pos - f;
            int lo = (int)f;
            if (lo > dc - 1) lo = dc - 1;
            if (lo < 0) lo = 0;
            int hi = lo + 1;
            if (hi > dc - 1) hi = dc - 1;
            aggd[3 + tid] = sv[lo] + frac * (sv[hi] - sv[lo]);
        }
        __syncthreads();

        float contrib = 0.f;
        if (tid < H_DIM) {
            float hj = bm1[tid];
            #pragma unroll
            for (int i = 0; i < 12; ++i)
                hj = fmaf(aggd[i], Wm1[i * H_DIM + tid], hj);
            hj = fmaxf(hj, 0.f);
            contrib = hj * Wm2[tid];
        }
        red[tid] = contrib;
        __syncthreads();
        for (int s = 256; s > 0; s >>= 1) {
            if (tid < s) red[tid] += red[tid + s];
            __syncthreads();
        }
        if (tid == 0) out[dseg] = red[0] + bm2[0];
        __syncthreads();
    }
}

// ---------------------------------------------------------------------------
extern "C" void kernel_launch(void* const* d_in, const int* in_sizes, int n_in,
                              void* d_out, int out_size)
{
    const float4* emb4   = (const float4*)d_in[0];
    const int*    batch  = (const int*)  d_in[1];
    const float*  W_lins = (const float*)d_in[2];
    const float*  b_lins = (const float*)d_in[3];
    const float*  W1     = (const float*)d_in[4];
    const float*  b1     = (const float*)d_in[5];
    const float*  W2     = (const float*)d_in[6];
    const float*  b2     = (const float*)d_in[7];
    const float*  Wm1    = (const float*)d_in[8];
    const float*  bm1    = (const float*)d_in[9];
    const float*  Wm2    = (const float*)d_in[10];
    const float*  bm2    = (const float*)d_in[11];
    float* out = (float*)d_out;

    static int nsm = 0;
    if (nsm == 0) {
        cudaDeviceGetAttribute(&nsm, cudaDevAttrMultiProcessorCount, 0);
        if (nsm <= 0) nsm = 148;
        cudaFuncSetAttribute(k_fused, cudaFuncAttributeMaxDynamicSharedMemorySize, SMEM_K1);
    }

    k_fused<<<nsm, 512, SMEM_K1>>>(emb4, batch, W_lins, b_lins, W1, b1, W2, b2,
                                   Wm1, bm1, Wm2, bm2, out);
}